// round 10
// baseline (speedup 1.0000x reference)
#include <cuda_runtime.h>

#define BB 32
#define TT 1024
#define II 256
#define HH 512
#define OO 1000
#define NBLK 128
#define RT 256
typedef unsigned long long ull_t;

__device__ float g_xg[(size_t)BB * TT * 4 * HH];   // gate pre-acts, layout [t][n][b]
__device__ float g_h1[(size_t)BB * TT * HH];
__device__ float g_h2[(size_t)BB * TT * HH];
// h double buffer: [(k>>1)][bhalf][b16][k&1]
__device__ float g_hb[2][HH * BB];
__device__ unsigned g_ctr[6];

__device__ __forceinline__ unsigned ld_acq(const unsigned* p) {
    unsigned v;
    asm volatile("ld.acquire.gpu.global.u32 %0, [%1];" : "=r"(v) : "l"(p) : "memory");
    return v;
}
__device__ __forceinline__ void red_rel(unsigned* p) {
    asm volatile("red.release.gpu.global.add.u32 [%0], 1;" :: "l"(p) : "memory");
}
__device__ __forceinline__ void ffma2(ull_t& d, ull_t a, ull_t b) {
    asm("fma.rn.f32x2 %0, %1, %2, %0;" : "+l"(d) : "l"(a), "l"(b));
}
__device__ __forceinline__ float sum2(ull_t v) {
    return __uint_as_float((unsigned)v) + __uint_as_float((unsigned)(v >> 32));
}
__device__ __forceinline__ float sig_(float x) {
    return __fdividef(1.f, 1.f + __expf(-x));
}
__device__ __forceinline__ float tanh_(float x) {
    return 1.f - __fdividef(2.f, __expf(2.f * x) + 1.f);
}
__device__ __forceinline__ void gbar(int id) {
    asm volatile("bar.sync %0, 128;" :: "r"(id) : "memory");
}

// ---------------- GEMM (f32x2): C[t][n][b] = A @ W^T + bias ----------------
// BM=128, BN=64, BK=16. 256 threads: ty=tid>>4 -> 8 m-rows; tx=tid&15 -> n cols {tx,tx+16,tx+32,tx+48}.
// sA[m][20] (16 k used, pad for banks/alignment); sB[kp][130] as (k-pair, 2n) pairs.
#define SA_STRIDE 20
#define SB_STRIDE 130
template <int PERM>
__global__ void __launch_bounds__(256)
gemm_kernel(const float* __restrict__ A, const float* __restrict__ W,
            const float* __restrict__ b1, const float* __restrict__ b2,
            float* __restrict__ C, int M, int N, int K)
{
    __shared__ float sA[128 * SA_STRIDE];
    __shared__ float sB[8 * SB_STRIDE];
    const int tid = threadIdx.x;
    const int n0 = blockIdx.x * 64;
    const int tx = tid & 15, ty = tid >> 4;

    // loader indices
    const int ar0 = tid >> 2, aq = tid & 3;           // A: rows ar0 and ar0+64, k-quad aq
    const int br = tid >> 2, bq = tid & 3;            // B: n-local br, k-quad bq

    auto rowA = [&](int r) -> int {
        if (PERM == 1) return (r & 31) * TT + blockIdx.y * 4 + (r >> 5);
        else           return blockIdx.y * 128 + r;
    };
    const int rA0 = rowA(ar0), rA1 = rowA(ar0 + 64);

    ull_t acc[8][4];
#pragma unroll
    for (int i = 0; i < 8; i++)
#pragma unroll
        for (int j = 0; j < 4; j++) acc[i][j] = 0ull;

    // prologue loads (tile k0=0)
    float4 ra0 = *(const float4*)(A + (size_t)rA0 * K + aq * 4);
    float4 ra1 = *(const float4*)(A + (size_t)rA1 * K + aq * 4);
    float4 rb  = *(const float4*)(W + (size_t)(n0 + br) * K + bq * 4);

    for (int k0 = 0; k0 < K; k0 += 16) {
        // stage regs -> smem
        *(float4*)(sA + ar0 * SA_STRIDE + aq * 4) = ra0;
        *(float4*)(sA + (ar0 + 64) * SA_STRIDE + aq * 4) = ra1;
        *(float2*)(sB + (2 * bq) * SB_STRIDE + 2 * br) = make_float2(rb.x, rb.y);
        *(float2*)(sB + (2 * bq + 1) * SB_STRIDE + 2 * br) = make_float2(rb.z, rb.w);
        __syncthreads();

        const bool more = (k0 + 16) < K;
        if (more) {
            ra0 = *(const float4*)(A + (size_t)rA0 * K + k0 + 16 + aq * 4);
            ra1 = *(const float4*)(A + (size_t)rA1 * K + k0 + 16 + aq * 4);
            rb  = *(const float4*)(W + (size_t)(n0 + br) * K + k0 + 16 + bq * 4);
        }

#pragma unroll
        for (int kp2 = 0; kp2 < 4; kp2++) {
            ull_t bA[4], bB[4];
#pragma unroll
            for (int j = 0; j < 4; j++) {
                bA[j] = *(const ull_t*)(sB + (2 * kp2) * SB_STRIDE + 2 * (tx + 16 * j));
                bB[j] = *(const ull_t*)(sB + (2 * kp2 + 1) * SB_STRIDE + 2 * (tx + 16 * j));
            }
#pragma unroll
            for (int i = 0; i < 8; i++) {
                ulonglong2 av = *(const ulonglong2*)(sA + (ty * 8 + i) * SA_STRIDE + kp2 * 4);
#pragma unroll
                for (int j = 0; j < 4; j++) {
                    ffma2(acc[i][j], av.x, bA[j]);
                    ffma2(acc[i][j], av.y, bB[j]);
                }
            }
        }
        __syncthreads();
    }

    const int r0 = ty * 8;
    const int tglob = blockIdx.y * 4 + (r0 >> 5);
    const int b0 = r0 & 31;
#pragma unroll
    for (int j = 0; j < 4; j++) {
        int n = n0 + tx + 16 * j;
        float bias = b1[n];
        if (b2) bias += b2[n];
        float4 v0 = {sum2(acc[0][j]) + bias, sum2(acc[1][j]) + bias,
                     sum2(acc[2][j]) + bias, sum2(acc[3][j]) + bias};
        float4 v1 = {sum2(acc[4][j]) + bias, sum2(acc[5][j]) + bias,
                     sum2(acc[6][j]) + bias, sum2(acc[7][j]) + bias};
        float* cp = C + ((size_t)tglob * N + n) * BB + b0;
        *(float4*)cp = v0;
        *(float4*)(cp + 4) = v1;
    }
}

// stage this CTA's 32KB h slice (16 batches, all k) for group kh
__device__ __forceinline__ void stage_half(const float* hb, float* sh, int tl, int kh, int bhalf) {
    const float4* src = (const float4*)hb;
    float4 r[8];
#pragma unroll
    for (int i = 0; i < 8; i++) {
        int L = kh * 1024 + tl + i * 128;
        int k2 = L >> 3, f = L & 7;
        r[i] = __ldcg(src + k2 * 16 + bhalf * 8 + f);
    }
    float4* dst = (float4*)sh;
#pragma unroll
    for (int i = 0; i < 8; i++) dst[kh * 1024 + tl + i * 128] = r[i];
}

// ---------------- persistent LSTM ----------------
__global__ void __launch_bounds__(RT, 1)
lstm_kernel(const float* __restrict__ xg, const float* __restrict__ whh,
            float* __restrict__ hseq)
{
    extern __shared__ float sm[];
    float* sh = sm;
    float* sg = sm + 8192;
    ull_t* swu = (ull_t*)(sg + 1024);
    const int tid = threadIdx.x, lane = tid & 31, w = tid >> 5;
    const int jblk = blockIdx.x >> 1, bhalf = blockIdx.x & 1;
    const int j0 = jblk * 8;
    const int cw = w & 3, kh = w >> 2;
    const int sub = lane >> 4, b = lane & 15;
    unsigned* ctr = &g_ctr[bhalf];

    {
        ull_t* dst = swu + w * 1024;
#pragma unroll
        for (int i = 0; i < 32; i++) {
            int e = lane + i * 32;
            int k2 = e >> 3, colpos = e & 7;
            int colid = cw * 8 + colpos;
            int gate = colid & 3, jl = colid >> 2;
            dst[k2 * 8 + colpos] = *(const ull_t*)(whh + ((size_t)gate * HH + j0 + jl) * HH + kh * 256 + k2 * 2);
        }
    }
    __syncthreads();

    const longlong2* wp = (const longlong2*)(swu + w * 1024);
    float creg = 0.f;

    for (int t = 0; t < TT; t++) {
        float xgi = 0.f, xgf = 0.f, xgc = 0.f, xgo = 0.f;
        if (tid < 128) {
            const int jl = tid >> 4, bb = tid & 15, bg = bhalf * 16 + bb;
            const size_t xb = ((size_t)t * (4 * HH) + j0 + jl) * BB + bg;
            xgi = __ldcg(xg + xb);               xgf = __ldcg(xg + xb + HH * BB);
            xgc = __ldcg(xg + xb + 2 * HH * BB); xgo = __ldcg(xg + xb + 3 * HH * BB);
        }
        ull_t a0 = 0ull, a1 = 0ull, a2 = 0ull, a3 = 0ull;
        if (t > 0) {
            if (tid == 0) { unsigned tgt = (unsigned)t * 64u; while (ld_acq(ctr) < tgt) {} }
            __syncthreads();
            stage_half(g_hb[t & 1], sh, tid & 127, kh, bhalf);
            gbar(1 + kh);
            const ull_t* hb2 = (const ull_t*)sh + kh * 2048 + b;
#pragma unroll 8
            for (int k2 = 0; k2 < 128; k2++) {
                ull_t hv = hb2[k2 * 16];
                longlong2 wA = wp[k2 * 4 + sub * 2], wB = wp[k2 * 4 + sub * 2 + 1];
                ffma2(a0, hv, (ull_t)wA.x); ffma2(a1, hv, (ull_t)wA.y);
                ffma2(a2, hv, (ull_t)wB.x); ffma2(a3, hv, (ull_t)wB.y);
            }
        }
        {
            float* p = sg + kh * 512 + (cw * 8 + sub * 4) * 16 + b;
            p[0] = sum2(a0); p[16] = sum2(a1); p[32] = sum2(a2); p[48] = sum2(a3);
        }
        __syncthreads();
        if (tid < 128) {
            const int jl = tid >> 4, bb = tid & 15, bg = bhalf * 16 + bb;
            const int j = j0 + jl;
            float gi = xgi + sg[(jl * 4 + 0) * 16 + bb] + sg[512 + (jl * 4 + 0) * 16 + bb];
            float gf = xgf + sg[(jl * 4 + 1) * 16 + bb] + sg[512 + (jl * 4 + 1) * 16 + bb];
            float gc = xgc + sg[(jl * 4 + 2) * 16 + bb] + sg[512 + (jl * 4 + 2) * 16 + bb];
            float go = xgo + sg[(jl * 4 + 3) * 16 + bb] + sg[512 + (jl * 4 + 3) * 16 + bb];
            float iv = sig_(gi), fv = sig_(gf), gv = tanh_(gc), ov = sig_(go);
            creg = fmaf(fv, creg, iv * gv);
            float hv = ov * tanh_(creg);
            __stcg(&g_hb[(t + 1) & 1][(j >> 1) * 64 + bhalf * 32 + bb * 2 + (j & 1)], hv);
            hseq[((size_t)t * BB + bg) * HH + j] = hv;
        }
        if (t < TT - 1) {
            __syncthreads();
            if (tid == 0) red_rel(ctr);
        }
    }
}

// ---------------- persistent GRU ----------------
__global__ void __launch_bounds__(RT, 1)
gru_kernel(const float* __restrict__ xg, const float* __restrict__ whh,
           const float* __restrict__ bhh, float* __restrict__ hseq)
{
    extern __shared__ float sm[];
    float* sh = sm;
    float* sg = sm + 8192;
    ull_t* swu = (ull_t*)(sg + 768);
    const int tid = threadIdx.x, lane = tid & 31, w = tid >> 5;
    const int jblk = blockIdx.x >> 1, bhalf = blockIdx.x & 1;
    const int j0 = jblk * 8;
    const int cw = w & 3, kh = w >> 2;
    const int sub = lane >> 4, b = lane & 15;
    unsigned* ctr = &g_ctr[2 + bhalf];

    {
        ull_t* dst = swu + w * 1024;
#pragma unroll
        for (int i = 0; i < 32; i++) {
            int e = lane + i * 32;
            int k2 = e >> 3, colpos = e & 7;
            int s_ = colpos >> 2, q = colpos & 3;
            ull_t v = 0ull;
            if (q < 3) {
                int jl = cw * 2 + s_;
                v = *(const ull_t*)(whh + ((size_t)q * HH + j0 + jl) * HH + kh * 256 + k2 * 2);
            }
            dst[k2 * 8 + colpos] = v;
        }
    }
    __syncthreads();

    const longlong2* wp = (const longlong2*)(swu + w * 1024);

    for (int t = 0; t < TT; t++) {
        float xr = 0.f, xz = 0.f, xn = 0.f;
        if (tid < 128) {
            const int jl = tid >> 4, bb = tid & 15, bg = bhalf * 16 + bb;
            const size_t xb = ((size_t)t * (3 * HH) + j0 + jl) * BB + bg;
            xr = __ldcg(xg + xb);
            xz = __ldcg(xg + xb + HH * BB);
            xn = __ldcg(xg + xb + 2 * HH * BB);
        }
        ull_t a0 = 0ull, a1 = 0ull, a2 = 0ull;
        if (t > 0) {
            if (tid == 0) { unsigned tgt = (unsigned)t * 64u; while (ld_acq(ctr) < tgt) {} }
            __syncthreads();
            stage_half(g_hb[t & 1], sh, tid & 127, kh, bhalf);
            gbar(1 + kh);
            const ull_t* hb2 = (const ull_t*)sh + kh * 2048 + b;
#pragma unroll 8
            for (int k2 = 0; k2 < 128; k2++) {
                ull_t hv = hb2[k2 * 16];
                longlong2 wA = wp[k2 * 4 + sub * 2], wB = wp[k2 * 4 + sub * 2 + 1];
                ffma2(a0, hv, (ull_t)wA.x); ffma2(a1, hv, (ull_t)wA.y);
                ffma2(a2, hv, (ull_t)wB.x);
            }
        }
        {
            float* p = sg + kh * 384 + (cw * 2 + sub) * 3 * 16 + b;
            p[0] = sum2(a0); p[16] = sum2(a1); p[32] = sum2(a2);
        }
        __syncthreads();
        if (tid < 128) {
            const int jl = tid >> 4, bb = tid & 15, bg = bhalf * 16 + bb;
            const int j = j0 + jl;
            float hr = sg[(jl * 3 + 0) * 16 + bb] + sg[384 + (jl * 3 + 0) * 16 + bb] + bhh[j];
            float hz = sg[(jl * 3 + 1) * 16 + bb] + sg[384 + (jl * 3 + 1) * 16 + bb] + bhh[HH + j];
            float hn = sg[(jl * 3 + 2) * 16 + bb] + sg[384 + (jl * 3 + 2) * 16 + bb] + bhh[2 * HH + j];
            float r = sig_(xr + hr);
            float z = sig_(xz + hz);
            float n = tanh_(fmaf(r, hn, xn));
            float hprev = (t > 0) ? sh[(j >> 1) * 32 + bb * 2 + (j & 1)] : 0.f;
            float hv = fmaf(z, hprev, (1.f - z) * n);
            __stcg(&g_hb[(t + 1) & 1][(j >> 1) * 64 + bhalf * 32 + bb * 2 + (j & 1)], hv);
            hseq[((size_t)t * BB + bg) * HH + j] = hv;
        }
        if (t < TT - 1) {
            __syncthreads();
            if (tid == 0) red_rel(ctr);
        }
    }
}

// ---------------- persistent RNN-tanh ----------------
__global__ void __launch_bounds__(RT, 1)
rnn_kernel(const float* __restrict__ xg, const float* __restrict__ whh)
{
    extern __shared__ float sm[];
    float* sh = sm;
    float* sg = sm + 8192;
    ull_t* swu = (ull_t*)(sg + 256);
    const int tid = threadIdx.x, lane = tid & 31, w = tid >> 5;
    const int jblk = blockIdx.x >> 1, bhalf = blockIdx.x & 1;
    const int j0 = jblk * 8;
    const int cw = w & 3, kh = w >> 2;
    const int sub = lane >> 4, b = lane & 15;
    unsigned* ctr = &g_ctr[4 + bhalf];

    {
        ull_t* dst = swu + w * 256;
#pragma unroll
        for (int i = 0; i < 8; i++) {
            int e = lane + i * 32;
            int k2 = e >> 1, s_ = e & 1;
            int jl = cw * 2 + s_;
            dst[k2 * 2 + s_] = *(const ull_t*)(whh + (size_t)(j0 + jl) * HH + kh * 256 + k2 * 2);
        }
    }
    __syncthreads();

    const ull_t* wl = swu + w * 256;

    for (int t = 0; t < TT; t++) {
        float xv = 0.f;
        if (tid < 128) {
            const int jl = tid >> 4, bb = tid & 15, bg = bhalf * 16 + bb;
            xv = __ldcg(xg + ((size_t)t * HH + j0 + jl) * BB + bg);
        }
        ull_t a0 = 0ull, a1 = 0ull;
        if (t > 0) {
            if (tid == 0) { unsigned tgt = (unsigned)t * 64u; while (ld_acq(ctr) < tgt) {} }
            __syncthreads();
            stage_half(g_hb[t & 1], sh, tid & 127, kh, bhalf);
            gbar(1 + kh);
            const ull_t* hb2 = (const ull_t*)sh + kh * 2048 + b;
#pragma unroll 8
            for (int k2 = 0; k2 < 128; k2 += 2) {
                ffma2(a0, hb2[k2 * 16], wl[k2 * 2 + sub]);
                ffma2(a1, hb2[(k2 + 1) * 16], wl[(k2 + 1) * 2 + sub]);
            }
        }
        sg[kh * 128 + (cw * 2 + sub) * 16 + b] = sum2(a0) + sum2(a1);
        __syncthreads();
        if (tid < 128) {
            const int jl = tid >> 4, bb = tid & 15;
            const int j = j0 + jl;
            float hv = tanh_(xv + sg[jl * 16 + bb] + sg[128 + jl * 16 + bb]);
            __stcg(&g_hb[(t + 1) & 1][(j >> 1) * 64 + bhalf * 32 + bb * 2 + (j & 1)], hv);
        }
        if (t < TT - 1) {
            __syncthreads();
            if (tid == 0) red_rel(ctr);
        }
    }
}

__global__ void __launch_bounds__(128)
ln_kernel(float* __restrict__ x, const float* __restrict__ g, const float* __restrict__ b)
{
    __shared__ float red[4];
    const size_t base = (size_t)blockIdx.x * HH;
    const int tid = threadIdx.x;
    float4 v = *(float4*)(x + base + tid * 4);
    float s = v.x + v.y + v.z + v.w;
#pragma unroll
    for (int o = 16; o; o >>= 1) s += __shfl_xor_sync(0xffffffffu, s, o);
    if ((tid & 31) == 0) red[tid >> 5] = s;
    __syncthreads();
    float mu = (red[0] + red[1] + red[2] + red[3]) * (1.f / HH);
    float dx = v.x - mu, dy = v.y - mu, dz = v.z - mu, dw = v.w - mu;
    float q = dx*dx + dy*dy + dz*dz + dw*dw;
#pragma unroll
    for (int o = 16; o; o >>= 1) q += __shfl_xor_sync(0xffffffffu, q, o);
    __syncthreads();
    if ((tid & 31) == 0) red[tid >> 5] = q;
    __syncthreads();
    float rs = rsqrtf((red[0] + red[1] + red[2] + red[3]) * (1.f / HH) + 1e-5f);
    int c = tid * 4;
    float4 o4;
    o4.x = fmaf(dx * rs, g[c+0], b[c+0]);
    o4.y = fmaf(dy * rs, g[c+1], b[c+1]);
    o4.z = fmaf(dz * rs, g[c+2], b[c+2]);
    o4.w = fmaf(dw * rs, g[c+3], b[c+3]);
    *(float4*)(x + base + tid * 4) = o4;
}

__global__ void __launch_bounds__(256)
fc_kernel(const float* __restrict__ w, const float* __restrict__ bias, float* __restrict__ out)
{
    const float* hb = g_hb[0];
    const int b = blockIdx.y;
    const int o = blockIdx.x * 8 + (threadIdx.x >> 5);
    const int lane = threadIdx.x & 31;
    const int boff = (b >> 4) * 32 + (b & 15) * 2;
    float acc = 0.f;
    const float* wr = w + (size_t)o * HH;
#pragma unroll 4
    for (int k2 = lane; k2 < 256; k2 += 32) {
        float2 hp = *(const float2*)(hb + k2 * 64 + boff);
        acc = fmaf(hp.x, wr[2 * k2], acc);
        acc = fmaf(hp.y, wr[2 * k2 + 1], acc);
    }
#pragma unroll
    for (int off = 16; off; off >>= 1) acc += __shfl_xor_sync(0xffffffffu, acc, off);
    if (lane == 0) out[b * OO + o] = acc + bias[o];
}

__global__ void reset_kernel() {
    if (threadIdx.x < 6) g_ctr[threadIdx.x] = 0;
}

extern "C" void kernel_launch(void* const* d_in, const int* in_sizes, int n_in,
                              void* d_out, int out_size)
{
    (void)in_sizes; (void)n_in; (void)out_size;
    const float* x     = (const float*)d_in[0];
    const float* lw_ih = (const float*)d_in[1];
    const float* lw_hh = (const float*)d_in[2];
    const float* lb_ih = (const float*)d_in[3];
    const float* lb_hh = (const float*)d_in[4];
    const float* l1g   = (const float*)d_in[5];
    const float* l1b   = (const float*)d_in[6];
    const float* gw_ih = (const float*)d_in[7];
    const float* gw_hh = (const float*)d_in[8];
    const float* gb_ih = (const float*)d_in[9];
    const float* gb_hh = (const float*)d_in[10];
    const float* l2g   = (const float*)d_in[11];
    const float* l2b   = (const float*)d_in[12];
    const float* rw_ih = (const float*)d_in[13];
    const float* rw_hh = (const float*)d_in[14];
    const float* rb_ih = (const float*)d_in[15];
    const float* rb_hh = (const float*)d_in[16];
    const float* fc_w  = (const float*)d_in[17];
    const float* fc_b  = (const float*)d_in[18];
    float* out = (float*)d_out;

    float *xg, *h1, *h2;
    cudaGetSymbolAddress((void**)&xg, g_xg);
    cudaGetSymbolAddress((void**)&h1, g_h1);
    cudaGetSymbolAddress((void**)&h2, g_h2);

    const int smem_lstm = 8192 * 4 + 1024 * 4 + 8 * 1024 * 8;
    const int smem_gru  = 8192 * 4 + 768 * 4 + 8 * 1024 * 8;
    const int smem_rnn  = 8192 * 4 + 256 * 4 + 8 * 256 * 8;
    static int configured = 0;
    if (!configured) {
        cudaFuncSetAttribute(lstm_kernel, cudaFuncAttributeMaxDynamicSharedMemorySize, smem_lstm);
        cudaFuncSetAttribute(gru_kernel,  cudaFuncAttributeMaxDynamicSharedMemorySize, smem_gru);
        cudaFuncSetAttribute(rnn_kernel,  cudaFuncAttributeMaxDynamicSharedMemorySize, smem_rnn);
        configured = 1;
    }

    const int M = BB * TT;
    reset_kernel<<<1, 32>>>();
    gemm_kernel<1><<<dim3(4 * HH / 64, M / 128), 256>>>(x, lw_ih, lb_ih, lb_hh, xg, M, 4 * HH, II);
    reset_kernel<<<1, 32>>>();   // keeps lstm_kernel in ncu's profiled launch slot
    lstm_kernel<<<NBLK, RT, smem_lstm>>>(xg, lw_hh, h1);
    ln_kernel<<<M, 128>>>(h1, l1g, l1b);

    gemm_kernel<2><<<dim3(3 * HH / 64, M / 128), 256>>>(h1, gw_ih, gb_ih, nullptr, xg, M, 3 * HH, HH);
    gru_kernel<<<NBLK, RT, smem_gru>>>(xg, gw_hh, gb_hh, h2);
    ln_kernel<<<M, 128>>>(h2, l2g, l2b);

    gemm_kernel<2><<<dim3(HH / 64, M / 128), 256>>>(h2, rw_ih, rb_ih, rb_hh, xg, M, HH, HH);
    rnn_kernel<<<NBLK, RT, smem_rnn>>>(xg, rw_hh);

    fc_kernel<<<dim3(OO / 8, BB), 256>>>(fc_w, fc_b, out);
}